// round 11
// baseline (speedup 1.0000x reference)
#include <cuda_runtime.h>
#include <cuda_fp16.h>
#include <math.h>
#include <stdint.h>

#define NB 64
#define NC 512
#define NM 1024
#define NKW 5
#define LDT 40
#define TILE_BYTES (128 * LDT * 2)       // 10240
#define STAGE_BYTES (3 * TILE_BYTES)     // 30720
#define NSTAGE 3
#define SMEM_TOTAL (NSTAGE * STAGE_BYTES)  // 92160
#define NTPB 10                          // CTAs per batch

// Scratch
__device__ float g_pe[NC * NM];
__device__ float g_pemean[NC];
__device__ float g_y[NB * NC];
__device__ float g_nu[NB * NC];
__device__ float g_mu[NB * NC];
__device__ int   g_done1[NB];
__device__ int   g_done2[NB];
__device__ __align__(16) __half g_hs_hi[NB * NC * NM];
__device__ __align__(16) __half g_hs_lo[NB * NC * NM];
__device__ __align__(16) __half g_hb_hi[NB * NC * NM];
__device__ __align__(16) __half g_hb_lo[NB * NC * NM];

__constant__ int2 c_tp[10] = {{0,0},{0,1},{0,2},{0,3},{1,1},{1,2},{1,3},{2,2},{2,3},{3,3}};

// ---------------------------------------------------------------------------
// pe: fills g_pe, g_pemean; also re-zeros the per-batch flags (every launch,
// so graph replays start clean).
// ---------------------------------------------------------------------------
__global__ void pe_kernel() {
    __shared__ float red[8];
    int c = blockIdx.x;
    if (threadIdx.x == 0 && c < NB) { g_done1[c] = 0; g_done2[c] = 0; }
    int i = c >> 1;
    float dv = expf(-(float)(2 * i) * (logf(10000.0f) / (float)NC));
    bool is_sin = (c & 1) == 0;
    float s = 0.f;
    for (int m = threadIdx.x; m < NM; m += blockDim.x) {
        float ang = (float)m * dv;
        float v = is_sin ? sinf(ang) : cosf(ang);
        g_pe[c * NM + m] = v;
        s += v;
    }
    #pragma unroll
    for (int o = 16; o; o >>= 1) s += __shfl_xor_sync(0xffffffffu, s, o);
    if ((threadIdx.x & 31) == 0) red[threadIdx.x >> 5] = s;
    __syncthreads();
    if (threadIdx.x == 0) {
        float t = 0.f;
        #pragma unroll
        for (int k = 0; k < 8; k++) t += red[k];
        g_pemean[c] = t * (1.0f / NM);
    }
}

// ---------------------------------------------------------------------------
__device__ __forceinline__ uint32_t pack2h(__half a, __half b) {
    return (uint32_t)__half_as_ushort(a) | ((uint32_t)__half_as_ushort(b) << 16);
}
__device__ __forceinline__ void split4h(float v0, float v1, float v2, float v3,
                                        uint2* hi, uint2* lo) {
    __half h0 = __float2half_rn(v0), h1 = __float2half_rn(v1);
    __half h2 = __float2half_rn(v2), h3 = __float2half_rn(v3);
    __half l0 = __float2half_rn(v0 - __half2float(h0));
    __half l1 = __float2half_rn(v1 - __half2float(h1));
    __half l2 = __float2half_rn(v2 - __half2float(h2));
    __half l3 = __float2half_rn(v3 - __half2float(h3));
    *hi = make_uint2(pack2h(h0, h1), pack2h(h2, h3));
    *lo = make_uint2(pack2h(l0, l1), pack2h(l2, l3));
}
__device__ __forceinline__ uint32_t smem_u32(const void* p) {
    uint32_t a;
    asm("{ .reg .u64 t; cvta.to.shared.u64 t, %1; cvt.u32.u64 %0, t; }" : "=r"(a) : "l"(p));
    return a;
}
__device__ __forceinline__ void ldsm_x4(uint32_t* r, uint32_t addr) {
    asm volatile("ldmatrix.sync.aligned.m8n8.x4.shared.b16 {%0,%1,%2,%3}, [%4];"
                 : "=r"(r[0]), "=r"(r[1]), "=r"(r[2]), "=r"(r[3]) : "r"(addr));
}
__device__ __forceinline__ void mma16816(float* d, const uint32_t* a, const uint32_t* b) {
    asm volatile(
        "mma.sync.aligned.m16n8k16.row.col.f32.f16.f16.f32 "
        "{%0,%1,%2,%3}, {%4,%5,%6,%7}, {%8,%9}, {%0,%1,%2,%3};"
        : "+f"(d[0]), "+f"(d[1]), "+f"(d[2]), "+f"(d[3])
        : "r"(a[0]), "r"(a[1]), "r"(a[2]), "r"(a[3]), "r"(b[0]), "r"(b[1]));
}
__device__ __forceinline__ void cp16(uint32_t dst, const void* src) {
    asm volatile("cp.async.cg.shared.global [%0], [%1], 16;" :: "r"(dst), "l"(src) : "memory");
}
__device__ __forceinline__ void cp_commit() {
    asm volatile("cp.async.commit_group;" ::: "memory");
}
template <int N>
__device__ __forceinline__ void cp_wait() {
    asm volatile("cp.async.wait_group %0;" :: "n"(N) : "memory");
}

extern __shared__ char dsm[];

// ---------------------------------------------------------------------------
// Fused kernel: grid (10, 64). Phases per batch:
//   A: per-row mean of h (nu), y = nu + pemean        [rows c%10 == blockIdx.x]
//   B: gate (from y neighbors), mu, fp16 hi/lo planes [same rows]
//   C: SYRK GEMM + epilogue (R8-proven code)
// Cross-CTA sync within a batch via fenced atomic counters.
// ---------------------------------------------------------------------------
__global__ __launch_bounds__(256, 2) void fused_kernel(
    const float* __restrict__ h, const float* __restrict__ w,
    const float* __restrict__ bias, float* __restrict__ out) {
    int tid = threadIdx.x;
    int lane = tid & 31;
    int wid = tid >> 5;
    int t = blockIdx.x;                  // 0..9, also tile index for phase C
    int b = blockIdx.y;

    // ===== Phase A: row means =====
    for (int i = wid; ; i += 8) {
        int c = t + NTPB * i;
        if (c >= NC) break;
        const float4* h4 = (const float4*)(h + ((size_t)b * NC + c) * NM);
        float s = 0.f;
        #pragma unroll
        for (int j = 0; j < 8; j++) {
            float4 v = h4[lane + 32 * j];
            s += (v.x + v.y) + (v.z + v.w);
        }
        #pragma unroll
        for (int o = 16; o; o >>= 1) s += __shfl_xor_sync(0xffffffffu, s, o);
        if (lane == 0) {
            float nu = s * (1.0f / NM);
            g_nu[b * NC + c] = nu;
            g_y[b * NC + c]  = nu + g_pemean[c];
        }
    }
    __threadfence();
    __syncthreads();
    if (tid == 0) {
        atomicAdd(&g_done1[b], 1);
        while (atomicAdd(&g_done1[b], 0) < NTPB) __nanosleep(100);
    }
    __syncthreads();
    __threadfence();

    // ===== Phase B: gate + mu + planes =====
    for (int i = wid; ; i += 8) {
        int c = t + NTPB * i;
        if (c >= NC) break;
        float gate;
        if (lane == 0) {
            float acc = bias[c];
            #pragma unroll
            for (int k = 0; k < NKW; k++) {
                int cc = c + k - 2;
                float yv = (cc >= 0 && cc < NC) ? g_y[b * NC + cc] : 0.0f;
                acc = fmaf(yv, w[c * NKW + k], acc);
            }
            gate = 1.0f / (1.0f + expf(-acc));
            g_mu[b * NC + c] = gate * g_y[b * NC + c];
        }
        gate = __shfl_sync(0xffffffffu, gate, 0);
        size_t rb = ((size_t)b * NC + c) * NM;
        #pragma unroll 2
        for (int j = 0; j < 8; j++) {
            size_t e = rb + (lane + 32 * j) * 4;
            float4 hv = *(const float4*)(h + e);
            float4 pv = *(const float4*)(g_pe + (size_t)c * NM + (lane + 32 * j) * 4);
            uint2 hi, lo;
            split4h((hv.x + pv.x) * gate, (hv.y + pv.y) * gate,
                    (hv.z + pv.z) * gate, (hv.w + pv.w) * gate, &hi, &lo);
            *(uint2*)(g_hs_hi + e) = hi;
            *(uint2*)(g_hs_lo + e) = lo;
            split4h(hv.x, hv.y, hv.z, hv.w, &hi, &lo);
            *(uint2*)(g_hb_hi + e) = hi;
            *(uint2*)(g_hb_lo + e) = lo;
        }
    }
    __threadfence();
    __syncthreads();
    if (tid == 0) {
        atomicAdd(&g_done2[b], 1);
        while (atomicAdd(&g_done2[b], 0) < NTPB) __nanosleep(100);
    }
    __syncthreads();
    __threadfence();

    // ===== Phase C: SYRK (R8 code) =====
    int2 tp = c_tp[t];
    int row0 = tp.x * 128;
    int col0 = tp.y * 128;
    bool diag = (row0 == col0);
    uint32_t sb = smem_u32(dsm);
    int wm = (wid >> 2) * 64;
    int wn = (wid & 3) * 32;

    float acc[4][4][4];
    #pragma unroll
    for (int i = 0; i < 4; i++)
        #pragma unroll
        for (int j = 0; j < 4; j++)
            #pragma unroll
            for (int q = 0; q < 4; q++) acc[i][j][q] = 0.0f;

    int aRowOff = lane & 15;
    int aColOff = (lane >> 4) * 8;
    int bRowOff = (lane & 7) + ((lane >> 4) << 3);
    int bColOff = ((lane >> 3) & 1) * 8;

    const size_t rowbase = (size_t)b * NC;

    auto issue = [&](int s) {
        int part = s >> 5;
        int k0 = (s & 31) * 32;
        uint32_t dstbase = sb + (uint32_t)(s % NSTAGE) * STAGE_BYTES;
        #pragma unroll
        for (int it = 0; it < 6; it++) {
            int item = it * 256 + tid;
            int tt = item >> 9;          // 0:A_hi 1:B_hi 2:B_lo
            int r  = (item >> 2) & 127;
            int ch = item & 3;
            int row = (tt ? col0 : row0) + r;
            const __half* plane =
                part ? ((tt == 2) ? g_hb_lo : g_hb_hi)
                     : ((tt == 2) ? g_hs_lo : g_hs_hi);
            const void* src = plane + (rowbase + row) * NM + k0 + ch * 8;
            uint32_t dst = dstbase + (uint32_t)(tt * TILE_BYTES + r * 80 + ch * 16);
            cp16(dst, src);
        }
        cp_commit();
    };

    issue(0);
    issue(1);
    for (int s = 0; s < 64; s++) {
        if (s < 63) cp_wait<1>();
        else        cp_wait<0>();
        __syncthreads();
        if (s + 2 < 64) issue(s + 2);

        uint32_t base = sb + (uint32_t)(s % NSTAGE) * STAGE_BYTES;
        uint32_t uA  = base;
        uint32_t uBH = base + TILE_BYTES;
        uint32_t uBL = base + 2 * TILE_BYTES;

        #pragma unroll
        for (int ks = 0; ks < 2; ks++) {
            int k0 = ks * 16;
            uint32_t aAddrBase = (uint32_t)((k0 + aColOff) * 2);
            uint32_t bAddrBase = (uint32_t)((k0 + bColOff) * 2);

            uint32_t bh[4][2], bl[4][2];
            #pragma unroll
            for (int half = 0; half < 2; half++) {
                uint32_t roff = (uint32_t)((wn + half * 16 + bRowOff) * LDT * 2);
                uint32_t r4[4];
                ldsm_x4(r4, uBH + roff + bAddrBase);
                bh[half * 2 + 0][0] = r4[0]; bh[half * 2 + 0][1] = r4[1];
                bh[half * 2 + 1][0] = r4[2]; bh[half * 2 + 1][1] = r4[3];
                ldsm_x4(r4, uBL + roff + bAddrBase);
                bl[half * 2 + 0][0] = r4[0]; bl[half * 2 + 0][1] = r4[1];
                bl[half * 2 + 1][0] = r4[2]; bl[half * 2 + 1][1] = r4[3];
            }

            uint32_t af[4][4];
            #pragma unroll
            for (int fm = 0; fm < 4; fm++) {
                uint32_t addr = uA +
                    (uint32_t)((wm + fm * 16 + aRowOff) * LDT * 2) + aAddrBase;
                ldsm_x4(af[fm], addr);
            }

            #pragma unroll
            for (int fm = 0; fm < 4; fm++)
                #pragma unroll
                for (int fn = 0; fn < 4; fn++)
                    mma16816(acc[fm][fn], af[fm], bh[fn]);
            #pragma unroll
            for (int fm = 0; fm < 4; fm++)
                #pragma unroll
                for (int fn = 0; fn < 4; fn++)
                    mma16816(acc[fm][fn], af[fm], bl[fn]);
        }
    }

    // epilogue
    const float* mug = g_mu + b * NC;
    const float* nug = g_nu + b * NC;
    float* outb = out + (size_t)b * NC * NC;
    const float invM = 1.0f / (float)NM;

    float muR[8], nuR[8], muC[8], nuC[8];
    #pragma unroll
    for (int fm = 0; fm < 4; fm++) {
        int r = row0 + wm + fm * 16 + (lane >> 2);
        muR[fm * 2]     = mug[r];     nuR[fm * 2]     = nug[r];
        muR[fm * 2 + 1] = mug[r + 8]; nuR[fm * 2 + 1] = nug[r + 8];
    }
    #pragma unroll
    for (int fn = 0; fn < 4; fn++) {
        int c = col0 + wn + fn * 8 + (lane & 3) * 2;
        muC[fn * 2]     = mug[c];     nuC[fn * 2]     = nug[c];
        muC[fn * 2 + 1] = mug[c + 1]; nuC[fn * 2 + 1] = nug[c + 1];
    }

    #pragma unroll
    for (int fm = 0; fm < 4; fm++) {
        #pragma unroll
        for (int fn = 0; fn < 4; fn++) {
            #pragma unroll
            for (int q = 0; q < 4; q++) {
                int rr = fm * 2 + (q >> 1);
                int cc = fn * 2 + (q & 1);
                int rI = row0 + wm + fm * 16 + (lane >> 2) + (q >> 1) * 8;
                int cJ = col0 + wn + fn * 8 + (lane & 3) * 2 + (q & 1);
                float v = acc[fm][fn][q] * invM - muR[rr] * muC[cc] - nuR[rr] * nuC[cc];
                if (rI == cJ) v += 1e-8f;
                if (!diag || rI <= cJ) {
                    outb[(size_t)rI * NC + cJ] = v;
                    outb[(size_t)cJ * NC + rI] = v;
                }
            }
        }
    }
}

// ---------------------------------------------------------------------------
extern "C" void kernel_launch(void* const* d_in, const int* in_sizes, int n_in,
                              void* d_out, int out_size) {
    const float* h    = (const float*)d_in[0];
    const float* w    = (const float*)d_in[1];
    const float* bias = (const float*)d_in[2];
    float* out = (float*)d_out;

    static int init = 0;
    if (!init) {
        cudaFuncSetAttribute(fused_kernel, cudaFuncAttributeMaxDynamicSharedMemorySize,
                             SMEM_TOTAL);
        init = 1;
    }

    pe_kernel<<<NC, 256>>>();
    dim3 grid(NTPB, NB);
    fused_kernel<<<grid, 256, SMEM_TOTAL>>>(h, w, bias, out);
}

// round 13
// speedup vs baseline: 1.8883x; 1.8883x over previous
#include <cuda_runtime.h>
#include <cuda_fp16.h>
#include <math.h>
#include <stdint.h>

#define NB 64
#define NC 512
#define NM 1024
#define NKW 5
#define LDT 40                           // padded fp16 row stride (elems) -> 80B
#define TILE_BYTES (128 * LDT * 2)       // 10240
#define STAGE_BYTES (2 * TILE_BYTES)     // 20480  (A_hi, B_hi)
#define NSTAGE 4
#define SMEM_TOTAL (NSTAGE * STAGE_BYTES)  // 81920

// Scratch
__device__ float g_pe[NC * NM];
__device__ float g_y[NB * NC];
__device__ float g_nu[NB * NC];
__device__ float g_gate[NB * NC];
__device__ float g_mu[NB * NC];
// fp16 planes (64MB each)
__device__ __align__(16) __half g_hs[NB * NC * NM];
__device__ __align__(16) __half g_hb[NB * NC * NM];

__constant__ int2 c_tp[10] = {{0,0},{0,1},{0,2},{0,3},{1,1},{1,2},{1,3},{2,2},{2,3},{3,3}};

// ---------------------------------------------------------------------------
__global__ void pe_kernel() {
    int c = blockIdx.x;
    int i = c >> 1;
    float dv = expf(-(float)(2 * i) * (logf(10000.0f) / (float)NC));
    bool is_sin = (c & 1) == 0;
    for (int m = threadIdx.x; m < NM; m += blockDim.x) {
        float ang = (float)m * dv;
        g_pe[c * NM + m] = is_sin ? sinf(ang) : cosf(ang);
    }
}

__global__ void stats_kernel(const float* __restrict__ h) {
    int warp = (blockIdx.x * blockDim.x + threadIdx.x) >> 5;
    int lane = threadIdx.x & 31;
    if (warp >= NB * NC) return;
    int c = warp % NC;
    const float4* h4 = (const float4*)(h + (size_t)warp * NM);
    const float4* p4 = (const float4*)(g_pe + (size_t)c * NM);
    float sh = 0.f, sp = 0.f;
    for (int i = lane; i < NM / 4; i += 32) {
        float4 hv = h4[i];
        float4 pv = p4[i];
        sh += (hv.x + hv.y) + (hv.z + hv.w);
        sp += (pv.x + pv.y) + (pv.z + pv.w);
    }
    float sx = sh + sp;
    #pragma unroll
    for (int o = 16; o; o >>= 1) {
        sx += __shfl_xor_sync(0xffffffffu, sx, o);
        sh += __shfl_xor_sync(0xffffffffu, sh, o);
    }
    if (lane == 0) {
        g_y[warp]  = sx * (1.0f / NM);
        g_nu[warp] = sh * (1.0f / NM);
    }
}

__global__ void gate_kernel(const float* __restrict__ w, const float* __restrict__ bias) {
    int idx = blockIdx.x * blockDim.x + threadIdx.x;
    if (idx >= NB * NC) return;
    int b = idx / NC, c = idx % NC;
    float acc = bias[c];
    #pragma unroll
    for (int k = 0; k < NKW; k++) {
        int cc = c + k - 2;
        float yv = (cc >= 0 && cc < NC) ? g_y[b * NC + cc] : 0.0f;
        acc = fmaf(yv, w[c * NKW + k], acc);
    }
    float gate = 1.0f / (1.0f + expf(-acc));
    g_gate[idx] = gate;
    g_mu[idx]   = gate * g_y[idx];
}

// ---------------------------------------------------------------------------
__device__ __forceinline__ uint32_t pack2h(__half a, __half b) {
    return (uint32_t)__half_as_ushort(a) | ((uint32_t)__half_as_ushort(b) << 16);
}
__device__ __forceinline__ uint2 cvt4h(float v0, float v1, float v2, float v3) {
    return make_uint2(pack2h(__float2half_rn(v0), __float2half_rn(v1)),
                      pack2h(__float2half_rn(v2), __float2half_rn(v3)));
}

__global__ __launch_bounds__(256) void prep_kernel(const float* __restrict__ h) {
    int rowid = blockIdx.x;              // b*NC + c
    int c = rowid & (NC - 1);
    int t = threadIdx.x;
    size_t e = (size_t)rowid * NM + t * 4;
    float4 hv = *(const float4*)(h + e);
    float4 pv = *(const float4*)(g_pe + (size_t)c * NM + t * 4);
    float gg = g_gate[rowid];
    *(uint2*)(g_hs + e) = cvt4h((hv.x + pv.x) * gg, (hv.y + pv.y) * gg,
                                (hv.z + pv.z) * gg, (hv.w + pv.w) * gg);
    *(uint2*)(g_hb + e) = cvt4h(hv.x, hv.y, hv.z, hv.w);
}

// ---------------------------------------------------------------------------
__device__ __forceinline__ uint32_t smem_u32(const void* p) {
    uint32_t a;
    asm("{ .reg .u64 t; cvta.to.shared.u64 t, %1; cvt.u32.u64 %0, t; }" : "=r"(a) : "l"(p));
    return a;
}
__device__ __forceinline__ void ldsm_x4(uint32_t* r, uint32_t addr) {
    asm volatile("ldmatrix.sync.aligned.m8n8.x4.shared.b16 {%0,%1,%2,%3}, [%4];"
                 : "=r"(r[0]), "=r"(r[1]), "=r"(r[2]), "=r"(r[3]) : "r"(addr));
}
__device__ __forceinline__ void mma16816(float* d, const uint32_t* a, const uint32_t* b) {
    asm volatile(
        "mma.sync.aligned.m16n8k16.row.col.f32.f16.f16.f32 "
        "{%0,%1,%2,%3}, {%4,%5,%6,%7}, {%8,%9}, {%0,%1,%2,%3};"
        : "+f"(d[0]), "+f"(d[1]), "+f"(d[2]), "+f"(d[3])
        : "r"(a[0]), "r"(a[1]), "r"(a[2]), "r"(a[3]), "r"(b[0]), "r"(b[1]));
}
__device__ __forceinline__ void cp16(uint32_t dst, const void* src) {
    asm volatile("cp.async.cg.shared.global [%0], [%1], 16;" :: "r"(dst), "l"(src) : "memory");
}
__device__ __forceinline__ void cp_commit() {
    asm volatile("cp.async.commit_group;" ::: "memory");
}
template <int N>
__device__ __forceinline__ void cp_wait() {
    asm volatile("cp.async.wait_group %0;" :: "n"(N) : "memory");
}

extern __shared__ char dsm[];

__global__ __launch_bounds__(256, 2) void syrk_hmma5(float* __restrict__ out) {
    int tid = threadIdx.x;
    int lane = tid & 31;
    int wid = tid >> 5;
    int b = blockIdx.y;
    int2 tp = c_tp[blockIdx.x];
    int row0 = tp.x * 128;
    int col0 = tp.y * 128;
    bool diag = (row0 == col0);

    uint32_t sb = smem_u32(dsm);

    // warp tile: 64 x 32
    int wm = (wid >> 2) * 64;
    int wn = (wid & 3) * 32;

    float acc[4][4][4];
    #pragma unroll
    for (int i = 0; i < 4; i++)
        #pragma unroll
        for (int j = 0; j < 4; j++)
            #pragma unroll
            for (int q = 0; q < 4; q++) acc[i][j][q] = 0.0f;

    int aRowOff = lane & 15;
    int aColOff = (lane >> 4) * 8;
    int bRowOff = (lane & 7) + ((lane >> 4) << 3);
    int bColOff = ((lane >> 3) & 1) * 8;

    const size_t rowbase = (size_t)b * NC;

    // per-stage cp.async: 2 tiles (A, B), 512 cp16 each -> 4/thread
    auto issue = [&](int s) {
        int part = s >> 5;               // 0 = hs, 1 = hb
        int k0 = (s & 31) * 32;
        uint32_t dstbase = sb + (uint32_t)(s % NSTAGE) * STAGE_BYTES;
        const __half* plane = part ? g_hb : g_hs;
        #pragma unroll
        for (int it = 0; it < 4; it++) {
            int item = it * 256 + tid;   // [0, 1024)
            int t  = item >> 9;          // 0:A 1:B
            int r  = (item >> 2) & 127;
            int ch = item & 3;
            int row = (t ? col0 : row0) + r;
            const void* src = plane + (rowbase + row) * NM + k0 + ch * 8;
            uint32_t dst = dstbase + (uint32_t)(t * TILE_BYTES + r * 80 + ch * 16);
            cp16(dst, src);
        }
        cp_commit();
    };

    issue(0);
    issue(1);
    issue(2);
    for (int s = 0; s < 64; s++) {
        if (s < 62)      cp_wait<2>();   // group s complete
        else if (s < 63) cp_wait<1>();
        else             cp_wait<0>();
        __syncthreads();                 // also closes WAR on stage (s+3)%4
        if (s + 3 < 64) issue(s + 3);

        uint32_t base = sb + (uint32_t)(s % NSTAGE) * STAGE_BYTES;
        uint32_t uA = base;
        uint32_t uB = base + TILE_BYTES;

        #pragma unroll
        for (int ks = 0; ks < 2; ks++) {
            int k0 = ks * 16;
            uint32_t aAddrBase = (uint32_t)((k0 + aColOff) * 2);
            uint32_t bAddrBase = (uint32_t)((k0 + bColOff) * 2);

            uint32_t bf[4][2];
            #pragma unroll
            for (int half = 0; half < 2; half++) {
                uint32_t roff = (uint32_t)((wn + half * 16 + bRowOff) * LDT * 2);
                uint32_t r4[4];
                ldsm_x4(r4, uB + roff + bAddrBase);
                bf[half * 2 + 0][0] = r4[0]; bf[half * 2 + 0][1] = r4[1];
                bf[half * 2 + 1][0] = r4[2]; bf[half * 2 + 1][1] = r4[3];
            }

            uint32_t af[4][4];
            #pragma unroll
            for (int fm = 0; fm < 4; fm++) {
                uint32_t addr = uA +
                    (uint32_t)((wm + fm * 16 + aRowOff) * LDT * 2) + aAddrBase;
                ldsm_x4(af[fm], addr);
            }

            #pragma unroll
            for (int fm = 0; fm < 4; fm++)
                #pragma unroll
                for (int fn = 0; fn < 4; fn++)
                    mma16816(acc[fm][fn], af[fm], bf[fn]);
        }
    }

    // ---- epilogue ----
    const float* mug = g_mu + b * NC;
    const float* nug = g_nu + b * NC;
    float* outb = out + (size_t)b * NC * NC;
    const float invM = 1.0f / (float)NM;

    float muR[8], nuR[8], muC[8], nuC[8];
    #pragma unroll
    for (int fm = 0; fm < 4; fm++) {
        int r = row0 + wm + fm * 16 + (lane >> 2);
        muR[fm * 2]     = mug[r];     nuR[fm * 2]     = nug[r];
        muR[fm * 2 + 1] = mug[r + 8]; nuR[fm * 2 + 1] = nug[r + 8];
    }
    #pragma unroll
    for (int fn = 0; fn < 4; fn++) {
        int c = col0 + wn + fn * 8 + (lane & 3) * 2;
        muC[fn * 2]     = mug[c];     nuC[fn * 2]     = nug[c];
        muC[fn * 2 + 1] = mug[c + 1]; nuC[fn * 2 + 1] = nug[c + 1];
    }

    #pragma unroll
    for (int fm = 0; fm < 4; fm++) {
        #pragma unroll
        for (int fn = 0; fn < 4; fn++) {
            #pragma unroll
            for (int q = 0; q < 4; q++) {
                int rr = fm * 2 + (q >> 1);
                int cc = fn * 2 + (q & 1);
                int rI = row0 + wm + fm * 16 + (lane >> 2) + (q >> 1) * 8;
                int cJ = col0 + wn + fn * 8 + (lane & 3) * 2 + (q & 1);
                float v = acc[fm][fn][q] * invM - muR[rr] * muC[cc] - nuR[rr] * nuC[cc];
                if (rI == cJ) v += 1e-8f;
                if (!diag || rI <= cJ) {
                    outb[(size_t)rI * NC + cJ] = v;
                    outb[(size_t)cJ * NC + rI] = v;
                }
            }
        }
    }
}

// ---------------------------------------------------------------------------
extern "C" void kernel_launch(void* const* d_in, const int* in_sizes, int n_in,
                              void* d_out, int out_size) {
    const float* h    = (const float*)d_in[0];
    const float* w    = (const float*)d_in[1];
    const float* bias = (const float*)d_in[2];
    float* out = (float*)d_out;

    static int init = 0;
    if (!init) {
        cudaFuncSetAttribute(syrk_hmma5, cudaFuncAttributeMaxDynamicSharedMemorySize,
                             SMEM_TOTAL);
        init = 1;
    }

    pe_kernel<<<NC, 256>>>();
    stats_kernel<<<(NB * NC) / 8, 256>>>(h);
    gate_kernel<<<(NB * NC + 255) / 256, 256>>>(w, bias);
    prep_kernel<<<NB * NC, 256>>>(h);
    dim3 grid(10, NB);
    syrk_hmma5<<<grid, 256, SMEM_TOTAL>>>(out);
}